// round 9
// baseline (speedup 1.0000x reference)
#include <cuda_runtime.h>
#include <cuda_fp16.h>
#include <cstdint>
#include <cstddef>

#define N_CAP 50000
#define E_CAP 1600000
#define NCOL  640
#define DEG_CAP 128

// Scratch (static __device__ — no allocation in kernel_launch)
__device__ __half  gUh[(size_t)NCOL * 128];       // folded weights, n-major [col][k], fp16
__device__ float   gC[NCOL];
__device__ float   gXv[(size_t)N_CAP * 64];       // self message, fp32
// Lane-interleaved per-node packs (lane l, head h at index l*4+h):
__device__ __half2 gEA[(size_t)N_CAP * 128];      // A-head logits (dst side), fp16
__device__ __half2 gEB[(size_t)N_CAP * 128];      // B-head logits (src side), fp16
__device__ __half2 gEXn[(size_t)N_CAP * 32];      // neighbor message, fp16
__device__ int     gCount[N_CAP];
__device__ int     gBkt[(size_t)N_CAP * DEG_CAP]; // direct-bucketed adjacency

__device__ __forceinline__ uint32_t h2u(__half2 h) { return *(uint32_t*)&h; }
__device__ __forceinline__ __half2 u2h(uint32_t u) { return *(__half2*)&u; }

// ---------------------------------------------------------------------------
__global__ void zero_kernel(int N) {
    int i = blockIdx.x * blockDim.x + threadIdx.x;
    if (i < N) gCount[i] = 0;
}

// ---------------------------------------------------------------------------
// Single-pass adjacency build: slot = atomicAdd(count[dst]); bucket store.
// ---------------------------------------------------------------------------
__global__ void build_kernel(const int* __restrict__ src, const int* __restrict__ dst, int E) {
    int i = blockIdx.x * blockDim.x + threadIdx.x;
    if (i < E) {
        int d = dst[i];
        int p = atomicAdd(&gCount[d], 1);
        if (p < DEG_CAP) gBkt[(size_t)d * DEG_CAP + p] = src[i];
    }
}

// ---------------------------------------------------------------------------
// Tiled weight fold. Blocks 0-7: (head i, half) -> 128x64 product tile via smem.
// Blocks 8,9: copy Wv -> cols 256-319, Wn -> cols 576-639 (n-major, fp16).
// col layout: [A heads: 0-255 | Xv: 256-319 | B heads: 320-575 | Xn: 576-639]
// ---------------------------------------------------------------------------
__global__ __launch_bounds__(256) void prep2_kernel(const float* __restrict__ Wv,
                                                    const float* __restrict__ Wn,
                                                    const float* __restrict__ Wt,
                                                    const float* __restrict__ Wa) {
    int b = blockIdx.x;
    int tid = threadIdx.x;
    if (b < 8) {
        int i = b >> 1, half = b & 1;
        __shared__ float wt[128 * 64];   // Wt[i]: [k][m]
        __shared__ float wa[64 * 64];    // Wa[i] half: [m][j]
        for (int idx = tid; idx < 128 * 64; idx += 256) wt[idx] = Wt[(size_t)i * 8192 + idx];
        for (int idx = tid; idx < 64 * 64; idx += 256)
            wa[idx] = Wa[(size_t)i * 8192 + (half ? 64 * 64 : 0) + idx];
        __syncthreads();
        int j = tid & 63;
        int kq = tid >> 6;               // 0..3
        int colbase = (half ? 320 : 0) + i * 64 + j;
        for (int kk = 0; kk < 32; kk++) {
            int k = kq * 32 + kk;
            float s = 0.f;
            #pragma unroll 16
            for (int m = 0; m < 64; m++) s += wt[k * 64 + m] * wa[m * 64 + j];
            gUh[(size_t)colbase * 128 + k] = __float2half_rn(s);
        }
    } else {
        int which = b - 8;               // 0 -> Wv, 1 -> Wn
        const float* W = which ? Wn : Wv;
        int base = which ? 576 : 256;
        for (int idx = tid; idx < 128 * 64; idx += 256) {
            int k = idx >> 6, j = idx & 63;
            gUh[(size_t)(base + j) * 128 + k] = __float2half_rn(W[idx]);
        }
    }
}

// ---------------------------------------------------------------------------
// Bias vector c[640]
// ---------------------------------------------------------------------------
__global__ void bias_kernel(const float* __restrict__ bv, const float* __restrict__ bn,
                            const float* __restrict__ bt, const float* __restrict__ Wa,
                            const float* __restrict__ ba) {
    int tid = threadIdx.x;
    if (tid < NCOL) {
        float c;
        if (tid < 256) {
            int i = tid >> 6, j = tid & 63;
            const float* btp = bt + i * 64;
            const float* wa = Wa + (size_t)i * 128 * 64 + j;
            float s = ba[i * 64 + j];
            #pragma unroll 8
            for (int m = 0; m < 64; m++)
                s += btp[m] * (wa[m * 64] + wa[(64 + m) * 64]);
            c = s;
        } else if (tid < 320) {
            c = bv[tid - 256];
        } else if (tid < 576) {
            c = 0.f;
        } else {
            c = bn[tid - 576];
        }
        gC[tid] = c;
    }
}

// ---------------------------------------------------------------------------
// FP16 tensor-core GEMM: Y[M x 640] = X[M x 128] @ U[128 x 640] + c
// BM=128, BN=128, full K=128 resident in smem. 8 warps, 32x64 per warp,
// m16n8k16 f16 mma, fp32 accumulators. Routes by absolute column.
// ---------------------------------------------------------------------------
#define LDH 136   // half elements per smem row (stride)
#define GEMM_SMEM ((128 * LDH + 128 * LDH) * 2)

__global__ __launch_bounds__(256) void gemm_tc_kernel(const float* __restrict__ X, int M) {
    extern __shared__ __half smem_h[];
    __half* As_h = smem_h;                  // [128][136]
    __half* Bs_h = smem_h + 128 * LDH;      // [128][136]  (n-major: row=n, col=k)

    int tid = threadIdx.x;
    int bm = blockIdx.x * 128;
    int bnblk = blockIdx.y * 128;

    // --- A tile: 128 rows x 128 k, fp32 -> fp16 ---
    #pragma unroll
    for (int it = 0; it < 16; it++) {
        int idx = tid + it * 256;            // 0..4095 (4-half slots)
        int r = idx >> 5;
        int c4 = (idx & 31) << 2;
        float4 v = make_float4(0.f, 0.f, 0.f, 0.f);
        if (bm + r < M) v = *(const float4*)(X + (size_t)(bm + r) * 128 + c4);
        __half2 h01 = __floats2half2_rn(v.x, v.y);
        __half2 h23 = __floats2half2_rn(v.z, v.w);
        uint2 o = { h2u(h01), h2u(h23) };
        *(uint2*)(As_h + r * LDH + c4) = o;
    }
    // --- B tile: 128 n-rows x 128 k, direct fp16 copy ---
    #pragma unroll
    for (int it = 0; it < 8; it++) {
        int idx = tid + it * 256;            // 0..2047 float4 slots
        int n = idx >> 4;
        int k8 = (idx & 15) << 3;
        float4 v = *(const float4*)(gUh + (size_t)(bnblk + n) * 128 + k8);
        *(float4*)(Bs_h + n * LDH + k8) = v;
    }
    __syncthreads();

    int w = tid >> 5, lane = tid & 31;
    int g = lane >> 2, tig = lane & 3;
    int wm = (w >> 1) * 32;     // 4 warps along M
    int wn = (w & 1) * 64;      // 2 warps along N, 64 wide each

    float acc[2][8][4];
    #pragma unroll
    for (int mt = 0; mt < 2; mt++)
        #pragma unroll
        for (int nt = 0; nt < 8; nt++)
            #pragma unroll
            for (int q = 0; q < 4; q++) acc[mt][nt][q] = 0.f;

    #pragma unroll
    for (int kc = 0; kc < 8; kc++) {
        int kb = kc * 16;
        uint32_t a[2][4], b[8][2];
        #pragma unroll
        for (int mt = 0; mt < 2; mt++) {
            int r0 = wm + mt * 16 + g;
            a[mt][0] = *(uint32_t*)(As_h + r0 * LDH + kb + 2 * tig);
            a[mt][1] = *(uint32_t*)(As_h + (r0 + 8) * LDH + kb + 2 * tig);
            a[mt][2] = *(uint32_t*)(As_h + r0 * LDH + kb + 2 * tig + 8);
            a[mt][3] = *(uint32_t*)(As_h + (r0 + 8) * LDH + kb + 2 * tig + 8);
        }
        #pragma unroll
        for (int nt = 0; nt < 8; nt++) {
            int n0 = wn + nt * 8 + g;
            b[nt][0] = *(uint32_t*)(Bs_h + n0 * LDH + kb + 2 * tig);
            b[nt][1] = *(uint32_t*)(Bs_h + n0 * LDH + kb + 2 * tig + 8);
        }
        #pragma unroll
        for (int mt = 0; mt < 2; mt++)
            #pragma unroll
            for (int nt = 0; nt < 8; nt++) {
                asm volatile(
                    "mma.sync.aligned.m16n8k16.row.col.f32.f16.f16.f32 "
                    "{%0,%1,%2,%3}, {%4,%5,%6,%7}, {%8,%9}, {%0,%1,%2,%3};\n"
                    : "+f"(acc[mt][nt][0]), "+f"(acc[mt][nt][1]),
                      "+f"(acc[mt][nt][2]), "+f"(acc[mt][nt][3])
                    : "r"(a[mt][0]), "r"(a[mt][1]), "r"(a[mt][2]), "r"(a[mt][3]),
                      "r"(b[nt][0]), "r"(b[nt][1]));
            }
    }

    // --- Epilogue: add bias, route by absolute column ---
    #pragma unroll
    for (int nt = 0; nt < 8; nt++) {
        int cg = wn + nt * 8 + tig * 2;
        int col = bnblk + cg;                       // even
        float bx = gC[col];
        float by = gC[col + 1];
        int lp = (col & 63) >> 1;                   // lane-pair index within head
        #pragma unroll
        for (int mt = 0; mt < 2; mt++) {
            #pragma unroll
            for (int half_ : {0, 1}) {
                int r = bm + wm + mt * 16 + g + half_ * 8;
                if (r < M) {
                    float vx = acc[mt][nt][half_ * 2 + 0] + bx;
                    float vy = acc[mt][nt][half_ * 2 + 1] + by;
                    if (col < 256) {
                        int h = col >> 6;
                        gEA[(size_t)r * 128 + lp * 4 + h] = __floats2half2_rn(vx, vy);
                    } else if (col < 320) {
                        float2 o = {vx, vy};
                        *(float2*)(gXv + (size_t)r * 64 + (col - 256)) = o;
                    } else if (col < 576) {
                        int h = (col - 320) >> 6;
                        gEB[(size_t)r * 128 + lp * 4 + h] = __floats2half2_rn(vx, vy);
                    } else {
                        gEXn[(size_t)r * 32 + lp] = __floats2half2_rn(vx, vy);
                    }
                }
            }
        }
    }
}

// ---------------------------------------------------------------------------
// Aggregation: one warp per dst node, thread owns 2 channels (2l, 2l+1).
// Batched x4 mainloop; indices read from the fixed-capacity bucket row.
// ---------------------------------------------------------------------------
union PackH { float4 f; __half2 h[4]; };

__device__ __forceinline__ void edge_term(
    const PackH& pa, const PackH& pb, __half2 xnh, __half2 z, __half2 Kc2,
    float& denx, float& deny, float& numx, float& numy)
{
    __half2 t = __hadd2(__hadd2(__hmax2(__hadd2(pa.h[0], pb.h[0]), z),
                                __hmax2(__hadd2(pa.h[1], pb.h[1]), z)),
                        __hadd2(__hmax2(__hadd2(pa.h[2], pb.h[2]), z),
                                __hmax2(__hadd2(pa.h[3], pb.h[3]), z)));
    uint32_t eu;
    asm("ex2.approx.f16x2 %0, %1;" : "=r"(eu) : "r"(h2u(__hmul2(t, Kc2))));
    float2 g = __half22float2(u2h(eu));
    float2 xn = __half22float2(xnh);
    denx += g.x;
    deny += g.y;
    numx = fmaf(g.x, xn.x, numx);
    numy = fmaf(g.y, xn.y, numy);
}

__global__ __launch_bounds__(256) void aggregate_kernel(float* __restrict__ out, int N) {
    int w = (blockIdx.x * blockDim.x + threadIdx.x) >> 5;
    int lane = threadIdx.x & 31;
    if (w >= N) return;
    int c = lane * 2;

    PackH pa;
    pa.f = __ldg((const float4*)(gEA + (size_t)w * 128) + lane);
    float2 xv = *(const float2*)(gXv + (size_t)w * 64 + c);

    const __half2 z = __floats2half2_rn(0.f, 0.f);
    const __half2 Kc2 = __floats2half2_rn(0.36067376022224085f, 0.36067376022224085f);

    // Self term
    PackH ps;
    ps.f = __ldg((const float4*)(gEB + (size_t)w * 128) + lane);
    __half2 t = __hadd2(__hadd2(__hmax2(__hadd2(pa.h[0], ps.h[0]), z),
                                __hmax2(__hadd2(pa.h[1], ps.h[1]), z)),
                        __hadd2(__hmax2(__hadd2(pa.h[2], ps.h[2]), z),
                                __hmax2(__hadd2(pa.h[3], ps.h[3]), z)));
    uint32_t eu;
    asm("ex2.approx.f16x2 %0, %1;" : "=r"(eu) : "r"(h2u(__hmul2(t, Kc2))));
    float2 ef = __half22float2(u2h(eu));
    float denx = ef.x, deny = ef.y;
    float numx = ef.x * xv.x, numy = ef.y * xv.y;

    const int* bkt = gBkt + (size_t)w * DEG_CAP;
    int deg = gCount[w];
    if (deg > DEG_CAP) deg = DEG_CAP;
    int j = 0;

    // Batched x4: issue all loads up front, then compute
    for (; j + 4 <= deg; j += 4) {
        int s0 = __ldg(bkt + j + 0);
        int s1 = __ldg(bkt + j + 1);
        int s2 = __ldg(bkt + j + 2);
        int s3 = __ldg(bkt + j + 3);
        PackH p0, p1, p2, p3;
        p0.f = __ldg((const float4*)(gEB + (size_t)s0 * 128) + lane);
        p1.f = __ldg((const float4*)(gEB + (size_t)s1 * 128) + lane);
        p2.f = __ldg((const float4*)(gEB + (size_t)s2 * 128) + lane);
        p3.f = __ldg((const float4*)(gEB + (size_t)s3 * 128) + lane);
        __half2 x0 = gEXn[(size_t)s0 * 32 + lane];
        __half2 x1 = gEXn[(size_t)s1 * 32 + lane];
        __half2 x2 = gEXn[(size_t)s2 * 32 + lane];
        __half2 x3 = gEXn[(size_t)s3 * 32 + lane];
        edge_term(pa, p0, x0, z, Kc2, denx, deny, numx, numy);
        edge_term(pa, p1, x1, z, Kc2, denx, deny, numx, numy);
        edge_term(pa, p2, x2, z, Kc2, denx, deny, numx, numy);
        edge_term(pa, p3, x3, z, Kc2, denx, deny, numx, numy);
    }
    for (; j < deg; j++) {
        int s = __ldg(bkt + j);
        PackH pb;
        pb.f = __ldg((const float4*)(gEB + (size_t)s * 128) + lane);
        __half2 xnh = gEXn[(size_t)s * 32 + lane];
        edge_term(pa, pb, xnh, z, Kc2, denx, deny, numx, numy);
    }

    float2 o;
    o.x = fmaxf(numx / denx, 0.f);
    o.y = fmaxf(numy / deny, 0.f);
    *(float2*)(out + (size_t)w * 64 + c) = o;
}

// ---------------------------------------------------------------------------
// Launch — adjacency build forked onto a side stream, overlapped with prep+GEMM.
// ---------------------------------------------------------------------------
static cudaStream_t g_s2 = nullptr;
static cudaEvent_t g_evFork = nullptr, g_evJoin = nullptr;

extern "C" void kernel_launch(void* const* d_in, const int* in_sizes, int n_in,
                              void* d_out, int out_size) {
    const float* x   = (const float*)d_in[0];
    const int*   src = (const int*)d_in[1];
    const int*   dst = (const int*)d_in[2];
    const float* Wv  = (const float*)d_in[3];
    const float* bv  = (const float*)d_in[4];
    const float* Wn  = (const float*)d_in[5];
    const float* bn  = (const float*)d_in[6];
    const float* Wt  = (const float*)d_in[7];
    const float* bt  = (const float*)d_in[8];
    const float* Wa  = (const float*)d_in[9];
    const float* ba  = (const float*)d_in[10];
    float* out = (float*)d_out;

    int N = in_sizes[0] / 128;
    int E = in_sizes[1];

    if (g_s2 == nullptr) {
        cudaFuncSetAttribute(gemm_tc_kernel,
                             cudaFuncAttributeMaxDynamicSharedMemorySize, GEMM_SMEM);
        cudaStreamCreateWithFlags(&g_s2, cudaStreamNonBlocking);
        cudaEventCreateWithFlags(&g_evFork, cudaEventDisableTiming);
        cudaEventCreateWithFlags(&g_evJoin, cudaEventDisableTiming);
    }

    // Fork side stream off the (possibly capturing) default stream
    cudaEventRecord(g_evFork, 0);
    cudaStreamWaitEvent(g_s2, g_evFork, 0);

    // Side stream: adjacency build (depends only on src/dst)
    zero_kernel<<<(N + 255) / 256, 256, 0, g_s2>>>(N);
    build_kernel<<<(E + 255) / 256, 256, 0, g_s2>>>(src, dst, E);
    cudaEventRecord(g_evJoin, g_s2);

    // Main stream: weight fold + bias + node GEMM
    prep2_kernel<<<10, 256>>>(Wv, Wn, Wt, Wa);
    bias_kernel<<<1, NCOL>>>(bv, bn, bt, Wa, ba);
    dim3 gg((N + 127) / 128, NCOL / 128);
    gemm_tc_kernel<<<gg, 256, GEMM_SMEM>>>(x, N);

    // Join and aggregate
    cudaStreamWaitEvent(0, g_evJoin, 0);
    aggregate_kernel<<<(N * 32 + 255) / 256, 256>>>(out, N);
}

// round 10
// speedup vs baseline: 1.3675x; 1.3675x over previous
#include <cuda_runtime.h>
#include <cuda_fp16.h>
#include <cstdint>
#include <cstddef>

#define N_CAP 50000
#define E_CAP 1600000
#define NCOL  640

// Scratch (static __device__ — no allocation in kernel_launch)
__device__ __half  gUh[(size_t)NCOL * 128];       // folded weights, n-major [col][k], fp16
__device__ float   gC[NCOL];
__device__ float   gXv[(size_t)N_CAP * 64];       // self message, fp32
// Lane-interleaved per-node packs (lane l, head h at index l*4+h):
__device__ __half2 gEA[(size_t)N_CAP * 128];      // A-head logits (dst side), fp16
__device__ __half2 gEB[(size_t)N_CAP * 128];      // B-head logits (src side), fp16
__device__ __half2 gEXn[(size_t)N_CAP * 32];      // neighbor message, fp16
__device__ int     gCount[N_CAP];
__device__ int     gOff[N_CAP + 1];
__device__ int     gCur[N_CAP];
__device__ int     gCsr[E_CAP];

__device__ __forceinline__ uint32_t h2u(__half2 h) { return *(uint32_t*)&h; }
__device__ __forceinline__ __half2 u2h(uint32_t u) { return *(__half2*)&u; }

// ---------------------------------------------------------------------------
__global__ void zero_kernel(int N) {
    int i = blockIdx.x * blockDim.x + threadIdx.x;
    if (i < N) gCount[i] = 0;
}

// ---------------------------------------------------------------------------
// Fold weights into Uh[col][k] (fp16, n-major) and c[col] (fp32)
// col layout: [A heads: 0-255 | Xv: 256-319 | B heads: 320-575 | Xn: 576-639]
//   A_i = Wt_i @ Wa_i[0:64,:]    bias: ba_i + bt_i@(Wa_top + Wa_bot)
//   B_i = Wt_i @ Wa_i[64:128,:]  bias 0
// ---------------------------------------------------------------------------
__global__ void prep_kernel(const float* __restrict__ Wv, const float* __restrict__ bv,
                            const float* __restrict__ Wn, const float* __restrict__ bn,
                            const float* __restrict__ Wt, const float* __restrict__ bt,
                            const float* __restrict__ Wa, const float* __restrict__ ba) {
    int tid = blockIdx.x * blockDim.x + threadIdx.x;
    if (tid < 128 * NCOL) {
        int k = tid / NCOL;
        int col = tid % NCOL;
        float v;
        if (col < 256 || (col >= 320 && col < 576)) {
            int top = (col < 256) ? 1 : 0;
            int cc = top ? col : (col - 320);
            int i = (cc >> 6) & 3;
            int j = cc & 63;
            const float* wt = Wt + ((size_t)i * 128 + k) * 64;        // Wt[i][k][*]
            const float* wa = Wa + (size_t)i * 128 * 64 + (top ? 0 : 64 * 64) + j;
            float s = 0.f;
            #pragma unroll 8
            for (int m = 0; m < 64; m++) s += wt[m] * wa[m * 64];
            v = s;
        } else if (col < 320) {
            v = Wv[k * 64 + (col - 256)];
        } else {
            v = Wn[k * 64 + (col - 576)];
        }
        gUh[(size_t)col * 128 + k] = __float2half_rn(v);
    }
    if (tid < NCOL) {
        float c;
        if (tid < 256) {
            int i = tid >> 6, j = tid & 63;
            const float* btp = bt + i * 64;
            const float* wa = Wa + (size_t)i * 128 * 64 + j;
            float s = ba[i * 64 + j];
            #pragma unroll 8
            for (int m = 0; m < 64; m++)
                s += btp[m] * (wa[m * 64] + wa[(64 + m) * 64]);
            c = s;
        } else if (tid < 320) {
            c = bv[tid - 256];
        } else if (tid < 576) {
            c = 0.f;
        } else {
            c = bn[tid - 576];
        }
        gC[tid] = c;
    }
}

// ---------------------------------------------------------------------------
// FP16 tensor-core GEMM: Y[M x 640] = X[M x 128] @ U[128 x 640] + c
// BM=128, BN=128, full K=128 resident in smem. 8 warps, 32x64 per warp,
// m16n8k16 f16 mma, fp32 accumulators. Routes by absolute column.
// ---------------------------------------------------------------------------
#define LDH 136   // half elements per smem row (stride)
#define GEMM_SMEM ((128 * LDH + 128 * LDH) * 2)

__global__ __launch_bounds__(256) void gemm_tc_kernel(const float* __restrict__ X, int M) {
    extern __shared__ __half smem_h[];
    __half* As_h = smem_h;                  // [128][136]
    __half* Bs_h = smem_h + 128 * LDH;      // [128][136]  (n-major: row=n, col=k)

    int tid = threadIdx.x;
    int bm = blockIdx.x * 128;
    int bnblk = blockIdx.y * 128;

    // --- A tile: 128 rows x 128 k, fp32 -> fp16 ---
    #pragma unroll
    for (int it = 0; it < 16; it++) {
        int idx = tid + it * 256;            // 0..4095 (4-half slots)
        int r = idx >> 5;
        int c4 = (idx & 31) << 2;
        float4 v = make_float4(0.f, 0.f, 0.f, 0.f);
        if (bm + r < M) v = *(const float4*)(X + (size_t)(bm + r) * 128 + c4);
        __half2 h01 = __floats2half2_rn(v.x, v.y);
        __half2 h23 = __floats2half2_rn(v.z, v.w);
        uint2 o = { h2u(h01), h2u(h23) };
        *(uint2*)(As_h + r * LDH + c4) = o;
    }
    // --- B tile: 128 n-rows x 128 k, direct fp16 copy ---
    #pragma unroll
    for (int it = 0; it < 8; it++) {
        int idx = tid + it * 256;            // 0..2047 float4 slots
        int n = idx >> 4;
        int k8 = (idx & 15) << 3;
        float4 v = *(const float4*)(gUh + (size_t)(bnblk + n) * 128 + k8);
        *(float4*)(Bs_h + n * LDH + k8) = v;
    }
    __syncthreads();

    int w = tid >> 5, lane = tid & 31;
    int g = lane >> 2, tig = lane & 3;
    int wm = (w >> 1) * 32;     // 4 warps along M
    int wn = (w & 1) * 64;      // 2 warps along N, 64 wide each

    float acc[2][8][4];
    #pragma unroll
    for (int mt = 0; mt < 2; mt++)
        #pragma unroll
        for (int nt = 0; nt < 8; nt++)
            #pragma unroll
            for (int q = 0; q < 4; q++) acc[mt][nt][q] = 0.f;

    #pragma unroll
    for (int kc = 0; kc < 8; kc++) {
        int kb = kc * 16;
        uint32_t a[2][4], b[8][2];
        #pragma unroll
        for (int mt = 0; mt < 2; mt++) {
            int r0 = wm + mt * 16 + g;
            a[mt][0] = *(uint32_t*)(As_h + r0 * LDH + kb + 2 * tig);
            a[mt][1] = *(uint32_t*)(As_h + (r0 + 8) * LDH + kb + 2 * tig);
            a[mt][2] = *(uint32_t*)(As_h + r0 * LDH + kb + 2 * tig + 8);
            a[mt][3] = *(uint32_t*)(As_h + (r0 + 8) * LDH + kb + 2 * tig + 8);
        }
        #pragma unroll
        for (int nt = 0; nt < 8; nt++) {
            int n0 = wn + nt * 8 + g;
            b[nt][0] = *(uint32_t*)(Bs_h + n0 * LDH + kb + 2 * tig);
            b[nt][1] = *(uint32_t*)(Bs_h + n0 * LDH + kb + 2 * tig + 8);
        }
        #pragma unroll
        for (int mt = 0; mt < 2; mt++)
            #pragma unroll
            for (int nt = 0; nt < 8; nt++) {
                asm volatile(
                    "mma.sync.aligned.m16n8k16.row.col.f32.f16.f16.f32 "
                    "{%0,%1,%2,%3}, {%4,%5,%6,%7}, {%8,%9}, {%0,%1,%2,%3};\n"
                    : "+f"(acc[mt][nt][0]), "+f"(acc[mt][nt][1]),
                      "+f"(acc[mt][nt][2]), "+f"(acc[mt][nt][3])
                    : "r"(a[mt][0]), "r"(a[mt][1]), "r"(a[mt][2]), "r"(a[mt][3]),
                      "r"(b[nt][0]), "r"(b[nt][1]));
            }
    }

    // --- Epilogue: add bias, route by absolute column ---
    #pragma unroll
    for (int nt = 0; nt < 8; nt++) {
        int cg = wn + nt * 8 + tig * 2;
        int col = bnblk + cg;                       // even
        float bx = gC[col];
        float by = gC[col + 1];
        int lp = (col & 63) >> 1;                   // lane-pair index within head
        #pragma unroll
        for (int mt = 0; mt < 2; mt++) {
            #pragma unroll
            for (int half_ : {0, 1}) {
                int r = bm + wm + mt * 16 + g + half_ * 8;
                if (r < M) {
                    float vx = acc[mt][nt][half_ * 2 + 0] + bx;
                    float vy = acc[mt][nt][half_ * 2 + 1] + by;
                    if (col < 256) {
                        int h = col >> 6;
                        gEA[(size_t)r * 128 + lp * 4 + h] = __floats2half2_rn(vx, vy);
                    } else if (col < 320) {
                        float2 o = {vx, vy};
                        *(float2*)(gXv + (size_t)r * 64 + (col - 256)) = o;
                    } else if (col < 576) {
                        int h = (col - 320) >> 6;
                        gEB[(size_t)r * 128 + lp * 4 + h] = __floats2half2_rn(vx, vy);
                    } else {
                        gEXn[(size_t)r * 32 + lp] = __floats2half2_rn(vx, vy);
                    }
                }
            }
        }
    }
}

// ---------------------------------------------------------------------------
// CSR build (scalar — measured faster than int4 variants on these
// atomic/latency-bound kernels: scatter 24.9us scalar vs 30.1us int4)
// ---------------------------------------------------------------------------
__global__ void count_kernel(const int* __restrict__ dst, int E) {
    int i = blockIdx.x * blockDim.x + threadIdx.x;
    if (i < E) atomicAdd(&gCount[dst[i]], 1);
}

__global__ void scan_kernel(int N) {
    __shared__ int sm[1024];
    int tid = threadIdx.x;
    int chunk = (N + 1023) / 1024;
    int start = tid * chunk;
    int end = start + chunk;
    if (end > N) end = N;
    if (start > N) start = N;
    int s = 0;
    for (int i = start; i < end; i++) s += gCount[i];
    sm[tid] = s;
    __syncthreads();
    for (int off = 1; off < 1024; off <<= 1) {
        int v = (tid >= off) ? sm[tid - off] : 0;
        __syncthreads();
        sm[tid] += v;
        __syncthreads();
    }
    int run = (tid == 0) ? 0 : sm[tid - 1];
    for (int i = start; i < end; i++) {
        gOff[i] = run;
        gCur[i] = run;
        run += gCount[i];
    }
    if (tid == 1023) gOff[N] = sm[1023];
}

__global__ void scatter_kernel(const int* __restrict__ src, const int* __restrict__ dst, int E) {
    int i = blockIdx.x * blockDim.x + threadIdx.x;
    if (i < E) {
        int p = atomicAdd(&gCur[dst[i]], 1);
        gCsr[p] = src[i];
    }
}

// ---------------------------------------------------------------------------
// Aggregation: one warp per dst node, thread owns 2 channels (2l, 2l+1).
// Batched x4 mainloop: all 8 data loads issued before any arithmetic.
// ---------------------------------------------------------------------------
union PackH { float4 f; __half2 h[4]; };

__device__ __forceinline__ void edge_term(
    const PackH& pa, const PackH& pb, __half2 xnh, __half2 z, __half2 Kc2,
    float& denx, float& deny, float& numx, float& numy)
{
    __half2 t = __hadd2(__hadd2(__hmax2(__hadd2(pa.h[0], pb.h[0]), z),
                                __hmax2(__hadd2(pa.h[1], pb.h[1]), z)),
                        __hadd2(__hmax2(__hadd2(pa.h[2], pb.h[2]), z),
                                __hmax2(__hadd2(pa.h[3], pb.h[3]), z)));
    uint32_t eu;
    asm("ex2.approx.f16x2 %0, %1;" : "=r"(eu) : "r"(h2u(__hmul2(t, Kc2))));
    float2 g = __half22float2(u2h(eu));
    float2 xn = __half22float2(xnh);
    denx += g.x;
    deny += g.y;
    numx = fmaf(g.x, xn.x, numx);
    numy = fmaf(g.y, xn.y, numy);
}

__global__ __launch_bounds__(256) void aggregate_kernel(float* __restrict__ out, int N) {
    int w = (blockIdx.x * blockDim.x + threadIdx.x) >> 5;
    int lane = threadIdx.x & 31;
    if (w >= N) return;
    int c = lane * 2;

    PackH pa;
    pa.f = ((const float4*)(gEA + (size_t)w * 128))[lane];
    float2 xv = *(const float2*)(gXv + (size_t)w * 64 + c);

    const __half2 z = __floats2half2_rn(0.f, 0.f);
    const __half2 Kc2 = __floats2half2_rn(0.36067376022224085f, 0.36067376022224085f);

    // Self term
    PackH ps;
    ps.f = ((const float4*)(gEB + (size_t)w * 128))[lane];
    __half2 t = __hadd2(__hadd2(__hmax2(__hadd2(pa.h[0], ps.h[0]), z),
                                __hmax2(__hadd2(pa.h[1], ps.h[1]), z)),
                        __hadd2(__hmax2(__hadd2(pa.h[2], ps.h[2]), z),
                                __hmax2(__hadd2(pa.h[3], ps.h[3]), z)));
    uint32_t eu;
    asm("ex2.approx.f16x2 %0, %1;" : "=r"(eu) : "r"(h2u(__hmul2(t, Kc2))));
    float2 ef = __half22float2(u2h(eu));
    float denx = ef.x, deny = ef.y;
    float numx = ef.x * xv.x, numy = ef.y * xv.y;

    int j = gOff[w];
    int end = gOff[w + 1];

    // Batched x4: issue all loads up front, then compute
    for (; j + 4 <= end; j += 4) {
        int s0 = gCsr[j + 0];
        int s1 = gCsr[j + 1];
        int s2 = gCsr[j + 2];
        int s3 = gCsr[j + 3];
        PackH p0, p1, p2, p3;
        p0.f = ((const float4*)(gEB + (size_t)s0 * 128))[lane];
        p1.f = ((const float4*)(gEB + (size_t)s1 * 128))[lane];
        p2.f = ((const float4*)(gEB + (size_t)s2 * 128))[lane];
        p3.f = ((const float4*)(gEB + (size_t)s3 * 128))[lane];
        __half2 x0 = gEXn[(size_t)s0 * 32 + lane];
        __half2 x1 = gEXn[(size_t)s1 * 32 + lane];
        __half2 x2 = gEXn[(size_t)s2 * 32 + lane];
        __half2 x3 = gEXn[(size_t)s3 * 32 + lane];
        edge_term(pa, p0, x0, z, Kc2, denx, deny, numx, numy);
        edge_term(pa, p1, x1, z, Kc2, denx, deny, numx, numy);
        edge_term(pa, p2, x2, z, Kc2, denx, deny, numx, numy);
        edge_term(pa, p3, x3, z, Kc2, denx, deny, numx, numy);
    }
    for (; j < end; j++) {
        int s = gCsr[j];
        PackH pb;
        pb.f = ((const float4*)(gEB + (size_t)s * 128))[lane];
        __half2 xnh = gEXn[(size_t)s * 32 + lane];
        edge_term(pa, pb, xnh, z, Kc2, denx, deny, numx, numy);
    }

    float2 o;
    o.x = fmaxf(numx / denx, 0.f);
    o.y = fmaxf(numy / deny, 0.f);
    *(float2*)(out + (size_t)w * 64 + c) = o;
}

// ---------------------------------------------------------------------------
// Launch — CSR build forked onto a side stream, overlapped with prep+GEMM.
// ---------------------------------------------------------------------------
static cudaStream_t g_s2 = nullptr;
static cudaEvent_t g_evFork = nullptr, g_evJoin = nullptr;

extern "C" void kernel_launch(void* const* d_in, const int* in_sizes, int n_in,
                              void* d_out, int out_size) {
    const float* x   = (const float*)d_in[0];
    const int*   src = (const int*)d_in[1];
    const int*   dst = (const int*)d_in[2];
    const float* Wv  = (const float*)d_in[3];
    const float* bv  = (const float*)d_in[4];
    const float* Wn  = (const float*)d_in[5];
    const float* bn  = (const float*)d_in[6];
    const float* Wt  = (const float*)d_in[7];
    const float* bt  = (const float*)d_in[8];
    const float* Wa  = (const float*)d_in[9];
    const float* ba  = (const float*)d_in[10];
    float* out = (float*)d_out;

    int N = in_sizes[0] / 128;
    int E = in_sizes[1];

    if (g_s2 == nullptr) {
        cudaFuncSetAttribute(gemm_tc_kernel,
                             cudaFuncAttributeMaxDynamicSharedMemorySize, GEMM_SMEM);
        cudaStreamCreateWithFlags(&g_s2, cudaStreamNonBlocking);
        cudaEventCreateWithFlags(&g_evFork, cudaEventDisableTiming);
        cudaEventCreateWithFlags(&g_evJoin, cudaEventDisableTiming);
    }

    // Fork side stream off the (possibly capturing) default stream
    cudaEventRecord(g_evFork, 0);
    cudaStreamWaitEvent(g_s2, g_evFork, 0);

    // Side stream: CSR build (depends only on src/dst)
    zero_kernel<<<(N + 255) / 256, 256, 0, g_s2>>>(N);
    count_kernel<<<(E + 255) / 256, 256, 0, g_s2>>>(dst, E);
    scan_kernel<<<1, 1024, 0, g_s2>>>(N);
    scatter_kernel<<<(E + 255) / 256, 256, 0, g_s2>>>(src, dst, E);
    cudaEventRecord(g_evJoin, g_s2);

    // Main stream: weight fold + node GEMM
    prep_kernel<<<(128 * NCOL + 255) / 256, 256>>>(Wv, bv, Wn, bn, Wt, bt, Wa, ba);
    dim3 gg((N + 127) / 128, NCOL / 128);
    gemm_tc_kernel<<<gg, 256, GEMM_SMEM>>>(x, N);

    // Join and aggregate
    cudaStreamWaitEvent(0, g_evJoin, 0);
    aggregate_kernel<<<(N * 32 + 255) / 256, 256>>>(out, N);
}